// round 4
// baseline (speedup 1.0000x reference)
#include <cuda_runtime.h>

// Fold (col2im): x (8, 32, 8, 8, 4096) f32, kernel (8,8), stride (4,4),
// n = 64 -> out (8, 32, 260, 260) f32.
//
// Vectorized gather: thread owns (bc, h, g) with g in [0,16]; for g<16 it
// computes 16 consecutive outputs w = 16g .. 16g+15 (w-quads wq = 4g..4g+3).
//
// out(w = 4*wq + r) gets:
//   w-branch A (wq<64):  x[di][dj=r  ][p1*64 + wq]
//   w-branch B (wq>=1):  x[di][dj=r+4][p1*64 + wq-1]
// crossed with h-branches:
//   h-branch A (q1<64):  di = r1,   p1 = q1
//   h-branch B (q1>=1):  di = r1+4, p1 = q1-1
//
// For each of the 8 dj planes per h-branch, p2 = 4g..4g+3 is one ALIGNED
// float4. The shifted element p2 = 4g-1 (needed for dj in 4..7, j=0) comes
// from a predicated scalar load that hits in L1 (same line as a neighboring
// lane's vector load). Tail group g=16 covers wq=64 (w 256..259), which only
// has w-branch-B contributions.

#define B_   8
#define C_   32
#define Npat 64
#define H_   260
#define W_   260
#define GPR  17      // w groups per row: 16 full (16 outputs) + 1 tail (4)
#define LDIM 4096

__global__ __launch_bounds__(256) void fold_v2_kernel(
    const float* __restrict__ x, float* __restrict__ out)
{
    const int TOTAL = B_ * C_ * H_ * GPR;   // 1,131,520
    int idx = blockIdx.x * blockDim.x + threadIdx.x;
    if (idx >= TOTAL) return;

    int g  = idx % GPR;
    int t  = idx / GPR;
    int h  = t % H_;
    int bc = t / H_;

    const int r1 = h & 3;
    const int q1 = h >> 2;
    const bool hA = (q1 < Npat);
    const bool hB = (q1 >= 1);

    const float* baseA = x + (size_t)(bc * 8 + r1)     * 8 * LDIM + q1 * Npat;
    const float* baseB = x + (size_t)(bc * 8 + r1 + 4) * 8 * LDIM + (q1 - 1) * Npat;
    const size_t orow = ((size_t)bc * H_ + h) * W_;

    if (g < 16) {
        float acc[16];
        #pragma unroll
        for (int i = 0; i < 16; i++) acc[i] = 0.f;
        const int p = 4 * g;

        #pragma unroll
        for (int br = 0; br < 2; br++) {
            const float* base = br ? baseB : baseA;
            const bool   v    = br ? hB    : hA;
            if (v) {
                // dj = 0..3 : aligned float4 at p2 = 4g (w-branch A)
                #pragma unroll
                for (int r = 0; r < 4; r++) {
                    float4 a = *reinterpret_cast<const float4*>(base + r * LDIM + p);
                    acc[0 + r] += a.x; acc[4 + r] += a.y;
                    acc[8 + r] += a.z; acc[12 + r] += a.w;
                }
                // dj = 4..7 : aligned float4 at p2 = 4g, plus scalar p2 = 4g-1
                #pragma unroll
                for (int r = 0; r < 4; r++) {
                    float4 b = *reinterpret_cast<const float4*>(base + (r + 4) * LDIM + p);
                    float prev = (g > 0) ? base[(r + 4) * LDIM + p - 1] : 0.f;
                    acc[0 + r] += prev; acc[4 + r] += b.x;
                    acc[8 + r] += b.y;  acc[12 + r] += b.z;
                }
            }
        }

        float* o = out + orow + 16 * g;
        #pragma unroll
        for (int j = 0; j < 4; j++)
            *reinterpret_cast<float4*>(o + 4 * j) =
                make_float4(acc[4 * j + 0], acc[4 * j + 1],
                            acc[4 * j + 2], acc[4 * j + 3]);
    } else {
        // Tail: wq = 64, w = 256..259. Only w-branch B (dj = r+4, p2 = 63).
        float4 v = make_float4(0.f, 0.f, 0.f, 0.f);
        if (hA) {
            v.x += baseA[4 * LDIM + 63]; v.y += baseA[5 * LDIM + 63];
            v.z += baseA[6 * LDIM + 63]; v.w += baseA[7 * LDIM + 63];
        }
        if (hB) {
            v.x += baseB[4 * LDIM + 63]; v.y += baseB[5 * LDIM + 63];
            v.z += baseB[6 * LDIM + 63]; v.w += baseB[7 * LDIM + 63];
        }
        *reinterpret_cast<float4*>(out + orow + 256) = v;
    }
}

extern "C" void kernel_launch(void* const* d_in, const int* in_sizes, int n_in,
                              void* d_out, int out_size)
{
    const float* x = (const float*)d_in[0];
    float* out = (float*)d_out;
    const int TOTAL = B_ * C_ * H_ * GPR;
    const int threads = 256;
    const int blocks = (TOTAL + threads - 1) / threads;
    fold_v2_kernel<<<blocks, threads>>>(x, out);
}

// round 5
// speedup vs baseline: 1.1635x; 1.1635x over previous
#include <cuda_runtime.h>

// Fold (col2im): x (8, 32, 8, 8, 4096) f32, kernel (8,8), stride (4,4),
// n = 64 -> out (8, 32, 260, 260) f32.
//
// v3: branch-free vector gather.
//  - thread (bc, h, g), g in 0..15, computes w = 16g..16g+15; lane 15 also
//    computes the tail w = 256..259.
//  - 16 unconditional LDG.128 per thread (invalid-edge addresses proven
//    in-bounds; contributions zeroed arithmetically via sA/sB).
//  - the shifted element p2 = 4g-1 comes from __shfl_up (lane g-1's b.w),
//    and the tail elements p2 = 63 are lane 15's own b.w -> no scalar loads.
//  - warp = exactly 2 rows x 16 lanes; fully convergent; .cs load/store hints.

#define LDIM 4096
#define H_   260
#define W_   260

__global__ __launch_bounds__(256) void fold_v3_kernel(
    const float* __restrict__ x, float* __restrict__ out)
{
    const int idx = blockIdx.x * 256 + threadIdx.x;   // grid exactly covers TOTAL
    const int g  = idx & 15;
    const int t  = idx >> 4;
    const int h  = t % H_;
    const int bc = t / H_;

    const int r1 = h & 3;
    const int q1 = h >> 2;

    const float sA  = (q1 < 64) ? 1.f : 0.f;   // h-branch A valid
    const float sB  = (q1 >= 1) ? 1.f : 0.f;   // h-branch B valid
    const float sP  = (g > 0)   ? 1.f : 0.f;   // prev (wq>=1) valid
    const float sAP = sA * sP;
    const float sBP = sB * sP;

    const float* baseA = x + (size_t)(bc * 8 + r1)     * 8 * LDIM + q1 * 64 + 4 * g;
    const float* baseB = x + (size_t)(bc * 8 + r1 + 4) * 8 * LDIM + (q1 - 1) * 64 + 4 * g;

    float acc[16];
    #pragma unroll
    for (int i = 0; i < 16; i++) acc[i] = 0.f;
    float tl[4] = {0.f, 0.f, 0.f, 0.f};

    // ---- h-branch A: di = r1, p1 = q1 ----
    #pragma unroll
    for (int r = 0; r < 4; r++) {                 // dj = 0..3 (w-branch A)
        float4 a = __ldcs(reinterpret_cast<const float4*>(baseA + r * LDIM));
        acc[r]      += sA * a.x;  acc[4 + r]  += sA * a.y;
        acc[8 + r]  += sA * a.z;  acc[12 + r] += sA * a.w;
    }
    #pragma unroll
    for (int r = 0; r < 4; r++) {                 // dj = 4..7 (w-branch B)
        float4 b = __ldcs(reinterpret_cast<const float4*>(baseA + (r + 4) * LDIM));
        float prev = __shfl_up_sync(0xffffffffu, b.w, 1, 16);
        acc[r]      += sAP * prev; acc[4 + r]  += sA * b.x;
        acc[8 + r]  += sA * b.y;   acc[12 + r] += sA * b.z;
        tl[r]       += sA * b.w;                  // tail (only lane 15 stores)
    }

    // ---- h-branch B: di = r1 + 4, p1 = q1 - 1 ----
    #pragma unroll
    for (int r = 0; r < 4; r++) {
        float4 a = __ldcs(reinterpret_cast<const float4*>(baseB + r * LDIM));
        acc[r]      += sB * a.x;  acc[4 + r]  += sB * a.y;
        acc[8 + r]  += sB * a.z;  acc[12 + r] += sB * a.w;
    }
    #pragma unroll
    for (int r = 0; r < 4; r++) {
        float4 b = __ldcs(reinterpret_cast<const float4*>(baseB + (r + 4) * LDIM));
        float prev = __shfl_up_sync(0xffffffffu, b.w, 1, 16);
        acc[r]      += sBP * prev; acc[4 + r]  += sB * b.x;
        acc[8 + r]  += sB * b.y;   acc[12 + r] += sB * b.z;
        tl[r]       += sB * b.w;
    }

    float* o = out + ((size_t)bc * H_ + h) * W_ + 16 * g;
    #pragma unroll
    for (int j = 0; j < 4; j++)
        __stcs(reinterpret_cast<float4*>(o + 4 * j),
               make_float4(acc[4 * j + 0], acc[4 * j + 1],
                           acc[4 * j + 2], acc[4 * j + 3]));
    if (g == 15)
        __stcs(reinterpret_cast<float4*>(o + 16),     // w = 256..259
               make_float4(tl[0], tl[1], tl[2], tl[3]));
}

extern "C" void kernel_launch(void* const* d_in, const int* in_sizes, int n_in,
                              void* d_out, int out_size)
{
    const float* x = (const float*)d_in[0];
    float* out = (float*)d_out;
    // TOTAL = 256 (bc) * 260 (h) * 16 (g) = 1,064,960 = 4160 * 256 exactly.
    fold_v3_kernel<<<4160, 256>>>(x, out);
}